// round 2
// baseline (speedup 1.0000x reference)
#include <cuda_runtime.h>
#include <math.h>

#define D_MODEL 2048
#define N_HEADS 16
#define DPH     128
#define D_FF    8192
#define BATCH   2
#define SEQ     2048
#define MROWS   (BATCH*SEQ)
#define HALF_DPH (DPH/2)

// ---------------- scratch (static device allocations; no cudaMalloc) ----------
__device__ float  g_xn[(size_t)MROWS*D_MODEL];
__device__ float  g_q [(size_t)MROWS*D_MODEL];
__device__ float  g_k [(size_t)MROWS*D_MODEL];
__device__ float  g_v [(size_t)MROWS*D_MODEL];
__device__ float  g_av[(size_t)MROWS*D_MODEL];
__device__ float  g_ao[(size_t)MROWS*D_MODEL];
__device__ float  g_h [(size_t)MROWS*D_FF];
__device__ float  g_logits[(size_t)BATCH*N_HEADS*SEQ*SEQ];
__device__ float2 g_sincos[(size_t)SEQ*HALF_DPH];

// ---------------- sin/cos table (fp64 to match numpy trig) --------------------
__global__ void sincos_kernel() {
    int idx = blockIdx.x * blockDim.x + threadIdx.x;
    if (idx >= SEQ * HALF_DPH) return;
    int t = idx / HALF_DPH;
    int i = idx % HALF_DPH;
    double invf = pow(10000.0, -(2.0 * i) / (double)DPH);
    double ang  = (double)t * invf;
    g_sincos[idx] = make_float2((float)sin(ang), (float)cos(ang));
}

// ---------------- layernorm ----------------------------------------------------
__global__ void layernorm_kernel(const float* __restrict__ x,
                                 const float* __restrict__ scale,
                                 const float* __restrict__ offset) {
    int row = blockIdx.x;
    const float* xr = x + (size_t)row * D_MODEL;
    float* o = g_xn + (size_t)row * D_MODEL;

    float s = 0.f, s2 = 0.f;
    for (int j = threadIdx.x; j < D_MODEL; j += blockDim.x) {
        float v = xr[j]; s += v; s2 += v * v;
    }
    __shared__ float red[64];
    #pragma unroll
    for (int off = 16; off; off >>= 1) {
        s  += __shfl_xor_sync(0xffffffffu, s,  off);
        s2 += __shfl_xor_sync(0xffffffffu, s2, off);
    }
    int wid = threadIdx.x >> 5, lid = threadIdx.x & 31;
    if (lid == 0) { red[wid] = s; red[wid + 32] = s2; }
    __syncthreads();
    if (threadIdx.x < 32) {
        int nw = blockDim.x >> 5;
        s  = (threadIdx.x < nw) ? red[threadIdx.x]      : 0.f;
        s2 = (threadIdx.x < nw) ? red[threadIdx.x + 32] : 0.f;
        #pragma unroll
        for (int off = 16; off; off >>= 1) {
            s  += __shfl_xor_sync(0xffffffffu, s,  off);
            s2 += __shfl_xor_sync(0xffffffffu, s2, off);
        }
        if (lid == 0) { red[0] = s; red[1] = s2; }
    }
    __syncthreads();
    float mean = red[0] / D_MODEL;
    float var  = red[1] / D_MODEL - mean * mean;
    float r    = rsqrtf(var + 1e-5f);
    for (int j = threadIdx.x; j < D_MODEL; j += blockDim.x)
        o[j] = scale[j] * r * (xr[j] - mean) + offset[j];
}

// ---------------- rotary (GPT-J rotate_every_two) ------------------------------
__global__ void rotary_kernel(float* __restrict__ q, float* __restrict__ k) {
    int idx = blockIdx.x * blockDim.x + threadIdx.x;
    if (idx >= MROWS * N_HEADS * HALF_DPH) return;
    int half = idx % HALF_DPH;
    int rest = idx / HALF_DPH;
    int h    = rest % N_HEADS;
    int row  = rest / N_HEADS;      // b*SEQ + s
    int t    = row % SEQ;
    float2 sc = g_sincos[t * HALF_DPH + half];
    size_t base = (size_t)row * D_MODEL + h * DPH + 2 * half;
    float q0 = q[base], q1 = q[base + 1];
    q[base]     = q0 * sc.y - q1 * sc.x;
    q[base + 1] = q1 * sc.y + q0 * sc.x;
    float k0 = k[base], k1 = k[base + 1];
    k[base]     = k0 * sc.y - k1 * sc.x;
    k[base + 1] = k1 * sc.y + k0 * sc.x;
}

// ---------------- GELU (tanh approximation, jax default) ------------------------
__device__ __forceinline__ float gelu_tanh(float x) {
    float x3 = x * x * x;
    float t = tanhf(0.7978845608028654f * (x + 0.044715f * x3));
    return 0.5f * x * (1.f + t);
}

// ---------------- tiled SGEMM --------------------------------------------------
// C = alpha * A * op(B)   (+ epilogue)
// A: [M,K] row-major (lda). B: NN -> [K,N] (ldb); NT -> [N,K] (ldb).
// EPI: 0 plain, 1 bias+gelu, 2 bias+add
// Batched via blockIdx.z: off = (z/hdiv)*s?b + (z%hdiv)*s?h
template<bool TRANSB, int EPI>
__global__ __launch_bounds__(256)
void gemm_kernel(const float* __restrict__ A, const float* __restrict__ B,
                 float* __restrict__ C,
                 const float* __restrict__ bias, const float* __restrict__ add,
                 int M, int N, int K, int lda, int ldb, int ldc,
                 long long sAb, long long sAh, long long sBb, long long sBh,
                 long long sCb, long long sCh, int hdiv, float alpha) {
    const int BM = 128, BN = 128, BK = 16;
    __shared__ float As[BK][BM];
    __shared__ float Bs[BK][BN];

    int z  = blockIdx.z;
    int bb = z / hdiv, hh = z % hdiv;
    A += (long long)bb * sAb + (long long)hh * sAh;
    B += (long long)bb * sBb + (long long)hh * sBh;
    C += (long long)bb * sCb + (long long)hh * sCh;

    int tid = threadIdx.x;
    int tx = tid & 15, ty = tid >> 4;
    int rowBase = blockIdx.y * BM;
    int colBase = blockIdx.x * BN;

    float acc[8][8];
    #pragma unroll
    for (int i = 0; i < 8; i++)
        #pragma unroll
        for (int j = 0; j < 8; j++) acc[i][j] = 0.f;

    for (int k0 = 0; k0 < K; k0 += BK) {
        // A tile: 128x16 = 512 float4, 2 per thread, store transposed As[k][m]
        #pragma unroll
        for (int l = 0; l < 2; l++) {
            int f  = tid + l * 256;
            int ar = f >> 2;
            int ak = (f & 3) << 2;
            float4 v = *reinterpret_cast<const float4*>(
                &A[(size_t)(rowBase + ar) * lda + k0 + ak]);
            As[ak + 0][ar] = v.x; As[ak + 1][ar] = v.y;
            As[ak + 2][ar] = v.z; As[ak + 3][ar] = v.w;
        }
        if (TRANSB) {
            // B: [N,K] -> Bs[k][n]
            #pragma unroll
            for (int l = 0; l < 2; l++) {
                int f  = tid + l * 256;
                int br = f >> 2;
                int bk = (f & 3) << 2;
                float4 v = *reinterpret_cast<const float4*>(
                    &B[(size_t)(colBase + br) * ldb + k0 + bk]);
                Bs[bk + 0][br] = v.x; Bs[bk + 1][br] = v.y;
                Bs[bk + 2][br] = v.z; Bs[bk + 3][br] = v.w;
            }
        } else {
            // B: [K,N] -> Bs[k][n] directly (vector store)
            #pragma unroll
            for (int l = 0; l < 2; l++) {
                int f  = tid + l * 256;
                int br = f >> 5;
                int bc = (f & 31) << 2;
                *reinterpret_cast<float4*>(&Bs[br][bc]) =
                    *reinterpret_cast<const float4*>(
                        &B[(size_t)(k0 + br) * ldb + colBase + bc]);
            }
        }
        __syncthreads();

        #pragma unroll
        for (int kk = 0; kk < BK; kk++) {
            float af[8], bf[8];
            #pragma unroll
            for (int i = 0; i < 8; i++) af[i] = As[kk][ty * 8 + i];
            #pragma unroll
            for (int j = 0; j < 8; j++) bf[j] = Bs[kk][tx * 8 + j];
            #pragma unroll
            for (int i = 0; i < 8; i++)
                #pragma unroll
                for (int j = 0; j < 8; j++)
                    acc[i][j] += af[i] * bf[j];
        }
        __syncthreads();
    }

    #pragma unroll
    for (int i = 0; i < 8; i++) {
        int r = rowBase + ty * 8 + i;
        #pragma unroll
        for (int j = 0; j < 8; j++) {
            int c = colBase + tx * 8 + j;
            float v = acc[i][j] * alpha;
            if (EPI == 1) { v += bias[c]; v = gelu_tanh(v); }
            if (EPI == 2) { v += bias[c] + add[(size_t)r * ldc + c]; }
            C[(size_t)r * ldc + c] = v;
        }
    }
}

// ---------------- masked softmax (in-place on g_logits) ------------------------
__global__ __launch_bounds__(256)
void softmax_kernel(const float* __restrict__ attn_bias) {
    long long r = blockIdx.x;            // over BATCH*N_HEADS*SEQ rows
    int i = (int)(r % SEQ);
    float* row = g_logits + r * SEQ;
    const float* brow = attn_bias + (size_t)i * SEQ;

    int tid = threadIdx.x;
    float vals[8];
    float mx = -INFINITY;
    #pragma unroll
    for (int l = 0; l < 8; l++) {
        int j = tid + l * 256;
        float v = row[j] + brow[j];
        if (j > i) v += -1e10f;
        vals[l] = v;
        mx = fmaxf(mx, v);
    }
    __shared__ float red[32];
    #pragma unroll
    for (int off = 16; off; off >>= 1)
        mx = fmaxf(mx, __shfl_xor_sync(0xffffffffu, mx, off));
    int wid = tid >> 5, lid = tid & 31;
    if (lid == 0) red[wid] = mx;
    __syncthreads();
    if (tid < 32) {
        mx = (tid < 8) ? red[tid] : -INFINITY;
        #pragma unroll
        for (int off = 4; off; off >>= 1)
            mx = fmaxf(mx, __shfl_xor_sync(0xffffffffu, mx, off));
        if (lid == 0) red[0] = mx;
    }
    __syncthreads();
    mx = red[0];

    float sum = 0.f;
    #pragma unroll
    for (int l = 0; l < 8; l++) { vals[l] = expf(vals[l] - mx); sum += vals[l]; }
    #pragma unroll
    for (int off = 16; off; off >>= 1)
        sum += __shfl_xor_sync(0xffffffffu, sum, off);
    if (lid == 0) red[wid] = sum;
    __syncthreads();
    if (tid < 32) {
        sum = (tid < 8) ? red[tid] : 0.f;
        #pragma unroll
        for (int off = 4; off; off >>= 1)
            sum += __shfl_xor_sync(0xffffffffu, sum, off);
        if (lid == 0) red[0] = sum;
    }
    __syncthreads();
    float inv = 1.f / red[0];
    #pragma unroll
    for (int l = 0; l < 8; l++)
        row[tid + l * 256] = vals[l] * inv;
}

// ---------------- launch --------------------------------------------------------
static float* symf(const void* s) {
    void* p = nullptr;
    cudaGetSymbolAddress(&p, s);
    return (float*)p;
}

extern "C" void kernel_launch(void* const* d_in, const int* in_sizes, int n_in,
                              void* d_out, int out_size) {
    (void)in_sizes; (void)n_in; (void)out_size;
    const float* x         = (const float*)d_in[0];
    const float* attn_bias = (const float*)d_in[1];
    const float* ln_scale  = (const float*)d_in[2];
    const float* ln_offset = (const float*)d_in[3];
    const float* wq        = (const float*)d_in[4];
    const float* wk        = (const float*)d_in[5];
    const float* wv        = (const float*)d_in[6];
    const float* wo        = (const float*)d_in[7];
    const float* w_fc_in   = (const float*)d_in[8];
    const float* b_fc_in   = (const float*)d_in[9];
    const float* w_fc_out  = (const float*)d_in[10];
    const float* b_fc_out  = (const float*)d_in[11];
    float* out = (float*)d_out;

    float* xn = symf(g_xn);
    float* q  = symf(g_q);
    float* k  = symf(g_k);
    float* v  = symf(g_v);
    float* av = symf(g_av);
    float* ao = symf(g_ao);
    float* hb = symf(g_h);
    float* lg = symf(g_logits);

    dim3 blk(256);

    sincos_kernel<<<(SEQ * HALF_DPH + 255) / 256, 256>>>();
    layernorm_kernel<<<MROWS, 256>>>(x, ln_scale, ln_offset);

    // Q/K/V projections: [4096,2048] x [2048,2048], NN
    dim3 g1(D_MODEL / 128, MROWS / 128, 1);
    gemm_kernel<false, 0><<<g1, blk>>>(xn, wq, q, nullptr, nullptr,
        MROWS, D_MODEL, D_MODEL, D_MODEL, D_MODEL, D_MODEL,
        0, 0, 0, 0, 0, 0, 1, 1.f);
    gemm_kernel<false, 0><<<g1, blk>>>(xn, wk, k, nullptr, nullptr,
        MROWS, D_MODEL, D_MODEL, D_MODEL, D_MODEL, D_MODEL,
        0, 0, 0, 0, 0, 0, 1, 1.f);
    gemm_kernel<false, 0><<<g1, blk>>>(xn, wv, v, nullptr, nullptr,
        MROWS, D_MODEL, D_MODEL, D_MODEL, D_MODEL, D_MODEL,
        0, 0, 0, 0, 0, 0, 1, 1.f);

    rotary_kernel<<<(MROWS * N_HEADS * HALF_DPH + 255) / 256, 256>>>(q, k);

    // logits[b,h] = q[b,:,h,:] @ k[b,:,h,:]^T / sqrt(DPH)   (NT, batched over b,h)
    dim3 g2(SEQ / 128, SEQ / 128, BATCH * N_HEADS);
    gemm_kernel<true, 0><<<g2, blk>>>(q, k, lg, nullptr, nullptr,
        SEQ, SEQ, DPH, D_MODEL, D_MODEL, SEQ,
        (long long)SEQ * D_MODEL, (long long)DPH,
        (long long)SEQ * D_MODEL, (long long)DPH,
        (long long)N_HEADS * SEQ * SEQ, (long long)SEQ * SEQ,
        N_HEADS, 0.08838834764831845f);

    softmax_kernel<<<BATCH * N_HEADS * SEQ, 256>>>(attn_bias);

    // attn_vec[b,:,h,:] = P[b,h] @ v[b,:,h,:]   (NN, batched over b,h)
    dim3 g3(DPH / 128, SEQ / 128, BATCH * N_HEADS);
    gemm_kernel<false, 0><<<g3, blk>>>(lg, v, av, nullptr, nullptr,
        SEQ, DPH, SEQ, SEQ, D_MODEL, D_MODEL,
        (long long)N_HEADS * SEQ * SEQ, (long long)SEQ * SEQ,
        (long long)SEQ * D_MODEL, (long long)DPH,
        (long long)SEQ * D_MODEL, (long long)DPH,
        N_HEADS, 1.f);

    // attn_out = attn_vec @ wo
    gemm_kernel<false, 0><<<g1, blk>>>(av, wo, ao, nullptr, nullptr,
        MROWS, D_MODEL, D_MODEL, D_MODEL, D_MODEL, D_MODEL,
        0, 0, 0, 0, 0, 0, 1, 1.f);

    // h = gelu(xn @ w_fc_in + b_fc_in)
    dim3 g4(D_FF / 128, MROWS / 128, 1);
    gemm_kernel<false, 1><<<g4, blk>>>(xn, w_fc_in, hb, b_fc_in, nullptr,
        MROWS, D_FF, D_MODEL, D_MODEL, D_FF, D_FF,
        0, 0, 0, 0, 0, 0, 1, 1.f);

    // out = h @ w_fc_out + b_fc_out + attn_out
    gemm_kernel<false, 2><<<g1, blk>>>(hb, w_fc_out, out, b_fc_out, ao,
        MROWS, D_MODEL, D_FF, D_FF, D_MODEL, D_MODEL,
        0, 0, 0, 0, 0, 0, 1, 1.f);
}

// round 7
// speedup vs baseline: 5.5221x; 5.5221x over previous
#include <cuda_runtime.h>
#include <cuda_fp16.h>
#include <math.h>
#include <stdint.h>

#define D_MODEL 2048
#define N_HEADS 16
#define DPH     128
#define D_FF    8192
#define BATCH   2
#define SEQ     2048
#define MROWS   (BATCH*SEQ)
#define HALFD   (DPH/2)
#define BH      (BATCH*N_HEADS)

// ---------------- scratch (static device arrays; no cudaMalloc) ----------------
__device__ __half g_xn16[(size_t)MROWS*D_MODEL];
__device__ float  g_qkv [(size_t)3*MROWS*D_MODEL];
__device__ __half g_q16 [(size_t)MROWS*D_MODEL];
__device__ __half g_k16 [(size_t)MROWS*D_MODEL];
__device__ __half g_v16t[(size_t)BH*DPH*SEQ];
__device__ float  g_logits[(size_t)BH*SEQ*SEQ];
__device__ __half g_p16 [(size_t)BH*SEQ*SEQ];
__device__ __half g_av16[(size_t)MROWS*D_MODEL];
__device__ float  g_ao  [(size_t)MROWS*D_MODEL];
__device__ __half g_h16 [(size_t)MROWS*D_FF];
__device__ __half g_wqkvt[(size_t)3*D_MODEL*D_MODEL];
__device__ __half g_wot [(size_t)D_MODEL*D_MODEL];
__device__ __half g_wfit[(size_t)D_FF*D_MODEL];
__device__ __half g_wfot[(size_t)D_MODEL*D_FF];
__device__ float2 g_sincos[(size_t)SEQ*HALFD];

// ---------------- family-portable PTX helpers -----------------------------------
__device__ __forceinline__ uint32_t smem_u32(const void* p) {
    uint32_t a;
    asm("{ .reg .u64 t; cvta.to.shared.u64 t, %1; cvt.u32.u64 %0, t; }" : "=r"(a) : "l"(p));
    return a;
}
__device__ __forceinline__ void cp_async16(uint32_t saddr, const void* gptr) {
    asm volatile("cp.async.cg.shared.global [%0], [%1], 16;" :: "r"(saddr), "l"(gptr));
}
__device__ __forceinline__ void cp_commit() {
    asm volatile("cp.async.commit_group;" ::: "memory");
}
template<int N>
__device__ __forceinline__ void cp_wait() {
    asm volatile("cp.async.wait_group %0;" :: "n"(N) : "memory");
}
__device__ __forceinline__ void ldsm_x4(uint32_t& r0, uint32_t& r1, uint32_t& r2, uint32_t& r3,
                                        uint32_t addr) {
    asm volatile("ldmatrix.sync.aligned.m8n8.x4.shared.b16 {%0,%1,%2,%3}, [%4];"
        : "=r"(r0), "=r"(r1), "=r"(r2), "=r"(r3) : "r"(addr));
}
__device__ __forceinline__ void mma16816(float& c0, float& c1, float& c2, float& c3,
                                         uint32_t a0, uint32_t a1, uint32_t a2, uint32_t a3,
                                         uint32_t b0, uint32_t b1) {
    asm volatile("mma.sync.aligned.m16n8k16.row.col.f32.f16.f16.f32 "
        "{%0,%1,%2,%3}, {%4,%5,%6,%7}, {%8,%9}, {%0,%1,%2,%3};"
        : "+f"(c0), "+f"(c1), "+f"(c2), "+f"(c3)
        : "r"(a0), "r"(a1), "r"(a2), "r"(a3), "r"(b0), "r"(b1));
}

// ---------------- small kernels -------------------------------------------------
__global__ void sincos_kernel() {
    int idx = blockIdx.x * blockDim.x + threadIdx.x;
    if (idx >= SEQ * HALFD) return;
    int t = idx / HALFD, i = idx % HALFD;
    double invf = pow(10000.0, -(2.0 * i) / (double)DPH);
    double ang  = (double)t * invf;
    g_sincos[idx] = make_float2((float)sin(ang), (float)cos(ang));
}

__global__ void layernorm_kernel(const float* __restrict__ x,
                                 const float* __restrict__ scale,
                                 const float* __restrict__ offset) {
    int row = blockIdx.x;
    const float* xr = x + (size_t)row * D_MODEL;
    __half* o = g_xn16 + (size_t)row * D_MODEL;
    float s = 0.f, s2 = 0.f;
    for (int j = threadIdx.x; j < D_MODEL; j += blockDim.x) {
        float v = xr[j]; s += v; s2 += v * v;
    }
    __shared__ float red[64];
    #pragma unroll
    for (int off = 16; off; off >>= 1) {
        s  += __shfl_xor_sync(0xffffffffu, s,  off);
        s2 += __shfl_xor_sync(0xffffffffu, s2, off);
    }
    int wid = threadIdx.x >> 5, lid = threadIdx.x & 31;
    if (lid == 0) { red[wid] = s; red[wid + 32] = s2; }
    __syncthreads();
    if (threadIdx.x < 32) {
        int nw = blockDim.x >> 5;
        s  = (threadIdx.x < nw) ? red[threadIdx.x]      : 0.f;
        s2 = (threadIdx.x < nw) ? red[threadIdx.x + 32] : 0.f;
        #pragma unroll
        for (int off = 16; off; off >>= 1) {
            s  += __shfl_xor_sync(0xffffffffu, s,  off);
            s2 += __shfl_xor_sync(0xffffffffu, s2, off);
        }
        if (lid == 0) { red[0] = s; red[1] = s2; }
    }
    __syncthreads();
    float mean = red[0] / D_MODEL;
    float var  = red[1] / D_MODEL - mean * mean;
    float r    = rsqrtf(var + 1e-5f);
    for (int j = threadIdx.x; j < D_MODEL; j += blockDim.x)
        o[j] = __float2half(scale[j] * r * (xr[j] - mean) + offset[j]);
}

// rotary: fp32 q/k -> fp16 q16/k16
__global__ void rotary_kernel(const float* __restrict__ q, const float* __restrict__ k) {
    int idx = blockIdx.x * blockDim.x + threadIdx.x;
    if (idx >= MROWS * N_HEADS * HALFD) return;
    int half = idx % HALFD;
    int rest = idx / HALFD;
    int h    = rest % N_HEADS;
    int row  = rest / N_HEADS;
    int t    = row % SEQ;
    float2 sc = g_sincos[t * HALFD + half];
    size_t base = (size_t)row * D_MODEL + h * DPH + 2 * half;
    float q0 = q[base], q1 = q[base + 1];
    g_q16[base]     = __float2half(q0 * sc.y - q1 * sc.x);
    g_q16[base + 1] = __float2half(q1 * sc.y + q0 * sc.x);
    float k0 = k[base], k1 = k[base + 1];
    g_k16[base]     = __float2half(k0 * sc.y - k1 * sc.x);
    g_k16[base + 1] = __float2half(k1 * sc.y + k0 * sc.x);
}

// weight transpose+convert: in[R][C] fp32 -> out[C][R] fp16
__global__ void tconv_kernel(const float* __restrict__ in, __half* __restrict__ out,
                             int R, int C) {
    __shared__ float t[32][33];
    int bx = blockIdx.x * 32, by = blockIdx.y * 32;
    int tx = threadIdx.x, ty = threadIdx.y;
    #pragma unroll
    for (int i = 0; i < 4; i++)
        t[ty + i * 8][tx] = in[(size_t)(by + ty + i * 8) * C + bx + tx];
    __syncthreads();
    #pragma unroll
    for (int i = 0; i < 4; i++)
        out[(size_t)(bx + ty + i * 8) * R + by + tx] = __float2half(t[tx][ty + i * 8]);
}

// V transpose: fp32 [b*S+t][h*128+d] -> v16t [bh][d][t] fp16
__global__ void vtrans_kernel(const float* __restrict__ v) {
    __shared__ float t[32][33];
    int z = blockIdx.z, bb = z >> 4, hh = z & 15;
    int tb = blockIdx.x * 32, db = blockIdx.y * 32;
    int tx = threadIdx.x, ty = threadIdx.y;
    #pragma unroll
    for (int i = 0; i < 4; i++)
        t[ty + i * 8][tx] = v[(size_t)(bb * SEQ + tb + ty + i * 8) * D_MODEL + hh * DPH + db + tx];
    __syncthreads();
    #pragma unroll
    for (int i = 0; i < 4; i++)
        g_v16t[((size_t)z * DPH + db + ty + i * 8) * SEQ + tb + tx] = __float2half(t[tx][ty + i * 8]);
}

__device__ __forceinline__ float gelu_tanh(float x) {
    float x3 = x * x * x;
    float t = tanhf(0.7978845608028654f * (x + 0.044715f * x3));
    return 0.5f * x * (1.f + t);
}

// masked softmax: fp32 logits (+bias, causal) -> fp16 probs
__global__ __launch_bounds__(256)
void softmax_kernel(const float* __restrict__ attn_bias) {
    long long r = blockIdx.x;
    int i = (int)(r % SEQ);
    const float* row = g_logits + r * SEQ;
    __half* prow = g_p16 + r * SEQ;
    const float* brow = attn_bias + (size_t)i * SEQ;
    int tid = threadIdx.x;
    float vals[8];
    float mx = -INFINITY;
    #pragma unroll
    for (int l = 0; l < 8; l++) {
        int j = tid + l * 256;
        float v = row[j] + brow[j];
        if (j > i) v += -1e10f;
        vals[l] = v;
        mx = fmaxf(mx, v);
    }
    __shared__ float red[32];
    #pragma unroll
    for (int off = 16; off; off >>= 1)
        mx = fmaxf(mx, __shfl_xor_sync(0xffffffffu, mx, off));
    int wid = tid >> 5, lid = tid & 31;
    if (lid == 0) red[wid] = mx;
    __syncthreads();
    if (tid < 32) {
        mx = (tid < 8) ? red[tid] : -INFINITY;
        #pragma unroll
        for (int off = 4; off; off >>= 1)
            mx = fmaxf(mx, __shfl_xor_sync(0xffffffffu, mx, off));
        if (lid == 0) red[0] = mx;
    }
    __syncthreads();
    mx = red[0];
    float sum = 0.f;
    #pragma unroll
    for (int l = 0; l < 8; l++) { vals[l] = expf(vals[l] - mx); sum += vals[l]; }
    #pragma unroll
    for (int off = 16; off; off >>= 1)
        sum += __shfl_xor_sync(0xffffffffu, sum, off);
    if (lid == 0) red[wid] = sum;
    __syncthreads();
    if (tid < 32) {
        sum = (tid < 8) ? red[tid] : 0.f;
        #pragma unroll
        for (int off = 4; off; off >>= 1)
            sum += __shfl_xor_sync(0xffffffffu, sum, off);
        if (lid == 0) red[0] = sum;
    }
    __syncthreads();
    float inv = 1.f / red[0];
    #pragma unroll
    for (int l = 0; l < 8; l++)
        prow[tid + l * 256] = __float2half(vals[l] * inv);
}

// ---------------- mma.sync fp16 GEMM (HMMA path; sm_103-baseline legal) ---------
// C[M,N] = alpha * A[M,K] @ Bt[N,K]^T (+ epilogue). A, Bt K-major fp16.
// CTA tile 128x128x32, 256 threads = 8 warps (2 m x 4 n), warp tile 64x32.
// cp.async double-buffered staging; smem rows padded to 80B (bank-conflict-free
// ldmatrix: 8 rows * 20 banks stride -> 8 distinct banks).
// EPI: 0 plain, 1 bias+gelu, 2 bias+add
#define SROW   80              // bytes per padded smem row (64B payload)
#define TILE_B (128 * SROW)    // 10240 per operand tile
#define STAGE_B (2 * TILE_B)   // A + B per stage

template<int EPI, typename CT>
__global__ __launch_bounds__(256)
void hgemm(const __half* __restrict__ A, const __half* __restrict__ Bt,
           CT* __restrict__ C, const float* __restrict__ bias,
           const float* __restrict__ add,
           int K, int lda, int ldb, int ldc,
           long long sAb, long long sAh, long long sBb, long long sBh,
           long long sCb, long long sCh, int hdiv, float alpha) {
    __shared__ __align__(16) char smem[2 * STAGE_B];   // 40 KB
    const uint32_t sbase = smem_u32(smem);
    int tid = threadIdx.x, wid = tid >> 5, lid = tid & 31;

    int z = blockIdx.z, bb = z / hdiv, hh = z % hdiv;
    A  += bb * sAb + hh * sAh;
    Bt += bb * sBb + hh * sBh;
    C  += bb * sCb + hh * sCh;
    int rowBase = blockIdx.y * 128;
    int colBase = blockIdx.x * 128;

    int wm = (wid >> 2) * 64;       // warp row offset (0/64)
    int wn = (wid & 3) * 32;        // warp col offset (0/32/64/96)

    float acc[4][4][4];
    #pragma unroll
    for (int i = 0; i < 4; i++)
        #pragma unroll
        for (int j = 0; j < 4; j++)
            #pragma unroll
            for (int c = 0; c < 4; c++) acc[i][j][c] = 0.f;

    // staging: 1024 16B chunks/stage (A 512 + B 512), 4 per thread
    const int NC = K >> 5;          // BK=32 chunks
    auto stage_load = [&](int st, int k0) {
        uint32_t base = sbase + st * STAGE_B;
        #pragma unroll
        for (int l = 0; l < 4; l++) {
            int c = tid + l * 256;
            int r  = (c & 511) >> 2;
            int kc = c & 3;
            if (c < 512)
                cp_async16(base + r * SROW + kc * 16,
                           A + (size_t)(rowBase + r) * lda + k0 + kc * 8);
            else
                cp_async16(base + TILE_B + r * SROW + kc * 16,
                           Bt + (size_t)(colBase + r) * ldb + k0 + kc * 8);
        }
        cp_commit();
    };

    stage_load(0, 0);

    for (int i = 0; i < NC; i++) {
        __syncthreads();  // all warps done computing the buffer about to be overwritten
        if (i + 1 < NC) { stage_load((i + 1) & 1, (i + 1) << 5); cp_wait<1>(); }
        else            { cp_wait<0>(); }
        __syncthreads();

        uint32_t abase = sbase + (i & 1) * STAGE_B;
        uint32_t bbase = abase + TILE_B;
        int which = lid >> 3, rim = lid & 7;

        #pragma unroll
        for (int ks = 0; ks < 2; ks++) {
            uint32_t a[4][4];
            #pragma unroll
            for (int mf = 0; mf < 4; mf++) {
                int r = wm + mf * 16 + ((which & 1) << 3) + rim;
                uint32_t addr = abase + r * SROW + ks * 32 + ((which >> 1) << 4);
                ldsm_x4(a[mf][0], a[mf][1], a[mf][2], a[mf][3], addr);
            }
            uint32_t b[4][2];
            #pragma unroll
            for (int np = 0; np < 2; np++) {
                int n = wn + np * 16 + ((which >> 1) << 3) + rim;
                uint32_t addr = bbase + n * SROW + ks * 32 + ((which & 1) << 4);
                uint32_t r0, r1, r2, r3;
                ldsm_x4(r0, r1, r2, r3, addr);
                b[np * 2][0] = r0; b[np * 2][1] = r1;
                b[np * 2 + 1][0] = r2; b[np * 2 + 1][1] = r3;
            }
            #pragma unroll
            for (int mf = 0; mf < 4; mf++)
                #pragma unroll
                for (int nf = 0; nf < 4; nf++)
                    mma16816(acc[mf][nf][0], acc[mf][nf][1], acc[mf][nf][2], acc[mf][nf][3],
                             a[mf][0], a[mf][1], a[mf][2], a[mf][3],
                             b[nf][0], b[nf][1]);
        }
    }

    // epilogue: fragment -> gmem (c0,c1 at row lid/4; c2,c3 at row lid/4+8)
    #pragma unroll
    for (int mf = 0; mf < 4; mf++) {
        #pragma unroll
        for (int nf = 0; nf < 4; nf++) {
            int col = colBase + wn + nf * 8 + (lid & 3) * 2;
            #pragma unroll
            for (int h = 0; h < 2; h++) {
                int row = rowBase + wm + mf * 16 + (lid >> 2) + h * 8;
                #pragma unroll
                for (int e = 0; e < 2; e++) {
                    float v = acc[mf][nf][h * 2 + e] * alpha;
                    int cc = col + e;
                    if (EPI == 1) { v += bias[cc]; v = gelu_tanh(v); }
                    if (EPI == 2) { v += bias[cc] + add[(size_t)row * ldc + cc]; }
                    if (sizeof(CT) == 2)
                        *reinterpret_cast<__half*>(&C[(size_t)row * ldc + cc]) = __float2half(v);
                    else
                        *reinterpret_cast<float*>(&C[(size_t)row * ldc + cc]) = v;
                }
            }
        }
    }
}

// ---------------- launch --------------------------------------------------------
static void* symp(const void* s) { void* p = nullptr; cudaGetSymbolAddress(&p, s); return p; }

extern "C" void kernel_launch(void* const* d_in, const int* in_sizes, int n_in,
                              void* d_out, int out_size) {
    (void)in_sizes; (void)n_in; (void)out_size;
    const float* x         = (const float*)d_in[0];
    const float* attn_bias = (const float*)d_in[1];
    const float* ln_scale  = (const float*)d_in[2];
    const float* ln_offset = (const float*)d_in[3];
    const float* wq        = (const float*)d_in[4];
    const float* wk        = (const float*)d_in[5];
    const float* wv        = (const float*)d_in[6];
    const float* wo        = (const float*)d_in[7];
    const float* w_fc_in   = (const float*)d_in[8];
    const float* b_fc_in   = (const float*)d_in[9];
    const float* w_fc_out  = (const float*)d_in[10];
    const float* b_fc_out  = (const float*)d_in[11];
    float* out = (float*)d_out;

    __half* xn16  = (__half*)symp(g_xn16);
    float*  qkv   = (float*)symp(g_qkv);
    __half* q16   = (__half*)symp(g_q16);
    __half* k16   = (__half*)symp(g_k16);
    __half* v16t  = (__half*)symp(g_v16t);
    float*  lg    = (float*)symp(g_logits);
    __half* p16   = (__half*)symp(g_p16);
    __half* av16  = (__half*)symp(g_av16);
    float*  ao    = (float*)symp(g_ao);
    __half* h16   = (__half*)symp(g_h16);
    __half* wqkvt = (__half*)symp(g_wqkvt);
    __half* wot   = (__half*)symp(g_wot);
    __half* wfit  = (__half*)symp(g_wfit);
    __half* wfot  = (__half*)symp(g_wfot);

    dim3 tb(32, 8), blk(256);

    sincos_kernel<<<(SEQ * HALFD + 255) / 256, 256>>>();
    // weight transposes -> fp16 K-major
    tconv_kernel<<<dim3(D_MODEL / 32, D_MODEL / 32), tb>>>(wq, wqkvt + 0 * (size_t)D_MODEL * D_MODEL, D_MODEL, D_MODEL);
    tconv_kernel<<<dim3(D_MODEL / 32, D_MODEL / 32), tb>>>(wk, wqkvt + 1 * (size_t)D_MODEL * D_MODEL, D_MODEL, D_MODEL);
    tconv_kernel<<<dim3(D_MODEL / 32, D_MODEL / 32), tb>>>(wv, wqkvt + 2 * (size_t)D_MODEL * D_MODEL, D_MODEL, D_MODEL);
    tconv_kernel<<<dim3(D_MODEL / 32, D_MODEL / 32), tb>>>(wo, wot, D_MODEL, D_MODEL);
    tconv_kernel<<<dim3(D_FF / 32, D_MODEL / 32), tb>>>(w_fc_in, wfit, D_MODEL, D_FF);
    tconv_kernel<<<dim3(D_MODEL / 32, D_FF / 32), tb>>>(w_fc_out, wfot, D_FF, D_MODEL);

    layernorm_kernel<<<MROWS, 256>>>(x, ln_scale, ln_offset);

    // fused QKV: z selects weight/output
    hgemm<0, float><<<dim3(D_MODEL / 128, MROWS / 128, 3), blk>>>(
        xn16, wqkvt, qkv, nullptr, nullptr,
        D_MODEL, D_MODEL, D_MODEL, D_MODEL,
        0, 0, (long long)D_MODEL * D_MODEL, 0, (long long)MROWS * D_MODEL, 0, 1, 1.f);

    rotary_kernel<<<(MROWS * N_HEADS * HALFD + 255) / 256, 256>>>(
        qkv, qkv + (size_t)MROWS * D_MODEL);
    vtrans_kernel<<<dim3(SEQ / 32, DPH / 32, BH), tb>>>(qkv + 2 * (size_t)MROWS * D_MODEL);

    // logits[bh] = q16 @ k16^T / sqrt(dph)
    hgemm<0, float><<<dim3(SEQ / 128, SEQ / 128, BH), blk>>>(
        q16, k16, lg, nullptr, nullptr,
        DPH, D_MODEL, D_MODEL, SEQ,
        (long long)SEQ * D_MODEL, (long long)DPH,
        (long long)SEQ * D_MODEL, (long long)DPH,
        (long long)N_HEADS * SEQ * SEQ, (long long)SEQ * SEQ,
        N_HEADS, 0.08838834764831845f);

    softmax_kernel<<<BH * SEQ, 256>>>(attn_bias);

    // attn_vec[bh] = P @ V
    hgemm<0, __half><<<dim3(DPH / 128, SEQ / 128, BH), blk>>>(
        p16, v16t, av16, nullptr, nullptr,
        SEQ, SEQ, SEQ, D_MODEL,
        (long long)N_HEADS * SEQ * SEQ, (long long)SEQ * SEQ,
        (long long)N_HEADS * DPH * SEQ, (long long)DPH * SEQ,
        (long long)SEQ * D_MODEL, (long long)DPH,
        N_HEADS, 1.f);

    // attn_out = attn_vec @ wo
    hgemm<0, float><<<dim3(D_MODEL / 128, MROWS / 128, 1), blk>>>(
        av16, wot, ao, nullptr, nullptr,
        D_MODEL, D_MODEL, D_MODEL, D_MODEL,
        0, 0, 0, 0, 0, 0, 1, 1.f);

    // h = gelu(xn @ w_fc_in + b_fc_in)  -> fp16
    hgemm<1, __half><<<dim3(D_FF / 128, MROWS / 128, 1), blk>>>(
        xn16, wfit, h16, b_fc_in, nullptr,
        D_MODEL, D_MODEL, D_MODEL, D_FF,
        0, 0, 0, 0, 0, 0, 1, 1.f);

    // out = h @ w_fc_out + b_fc_out + attn_out
    hgemm<2, float><<<dim3(D_MODEL / 128, MROWS / 128, 1), blk>>>(
        h16, wfot, out, b_fc_out, ao,
        D_FF, D_FF, D_FF, D_MODEL,
        0, 0, 0, 0, 0, 0, 1, 1.f);
}